// round 6
// baseline (speedup 1.0000x reference)
#include <cuda_runtime.h>
#include <math.h>
#include <stdint.h>

#define BATCH 2
#define SEQ   2048
#define DIM   1024
#define NH    16
#define HD    64
#define MTOT  (BATCH*SEQ)   // 4096

// ---------------------------------------------------------------------------
// Scratch (allocation-free rule: __device__ globals)
// ---------------------------------------------------------------------------
__device__ float g_q[MTOT*DIM];     // Q, pre-scaled by 1/sqrt(hd)
__device__ float g_khi[MTOT*DIM];   // K split: tf32 hi
__device__ float g_klo[MTOT*DIM];   // K split: tf32 lo
__device__ float g_v[MTOT*DIM];     // V, tf32-rounded
__device__ float g_a[MTOT*DIM];     // attention output (fp32)
// Transposed weights, stored as tf32 bit patterns: WT[n][k] = tf32(W[k][n])
__device__ float g_wqt[DIM*DIM];
__device__ float g_wkt[DIM*DIM];
__device__ float g_wvt[DIM*DIM];
__device__ float g_wot[DIM*DIM];

// ---------------------------------------------------------------------------
// Helpers
// ---------------------------------------------------------------------------
__device__ __forceinline__ uint32_t f2tf32(float f) {
    uint32_t u;
    asm("cvt.rna.tf32.f32 %0, %1;" : "=r"(u) : "f"(f));
    return u;
}
__device__ __forceinline__ uint32_t smem_u32(const void* p) {
    uint32_t a;
    asm("{ .reg .u64 t; cvta.to.shared.u64 t, %1; cvt.u32.u64 %0, t; }"
        : "=r"(a) : "l"(p));
    return a;
}

#define MMA_TF32(d, a, b) \
    asm volatile("mma.sync.aligned.m16n8k8.row.col.f32.tf32.tf32.f32 " \
        "{%0,%1,%2,%3}, {%4,%5,%6,%7}, {%8,%9}, {%0,%1,%2,%3};" \
        : "+f"((d)[0]), "+f"((d)[1]), "+f"((d)[2]), "+f"((d)[3]) \
        : "r"((a)[0]), "r"((a)[1]), "r"((a)[2]), "r"((a)[3]), \
          "r"((b)[0]), "r"((b)[1]))

#define CP_ASYNC16(dst_u32, src_ptr) \
    asm volatile("cp.async.cg.shared.global [%0], [%1], 16;" \
        :: "r"(dst_u32), "l"(src_ptr))
#define CP_COMMIT() asm volatile("cp.async.commit_group;" ::: "memory")
#define CP_WAIT0()  asm volatile("cp.async.wait_group 0;"  ::: "memory")

// ---------------------------------------------------------------------------
// Transpose + tf32-convert: W[K,N] fp32 -> WT[N,K] (tf32 bit patterns)
// ---------------------------------------------------------------------------
__global__ __launch_bounds__(256) void transpose_tf32_kernel(
    const float* __restrict__ W, float* __restrict__ WT)
{
    __shared__ float tile[32][33];
    const int k0 = blockIdx.y * 32;
    const int n0 = blockIdx.x * 32;
    const int tx = threadIdx.x;
    const int ty = threadIdx.y;
    #pragma unroll
    for (int i = ty; i < 32; i += 8)
        tile[i][tx] = W[(size_t)(k0 + i) * DIM + n0 + tx];
    __syncthreads();
    #pragma unroll
    for (int i = ty; i < 32; i += 8) {
        uint32_t u = f2tf32(tile[tx][i]);
        reinterpret_cast<uint32_t*>(WT)[(size_t)(n0 + i) * DIM + k0 + tx] = u;
    }
}

// ---------------------------------------------------------------------------
// tf32 tensor-core GEMM with epilogue modes:
//   mode 0: C = v + bias               (output projection)
//   mode 1: C = v * 0.125              (Q, pre-scaled)
//   mode 2: C = tf32_hi(v), C2 = tf32_lo(v)   (K, pre-split)
//   mode 3: C = tf32(v)                (V, pre-rounded)
// ---------------------------------------------------------------------------
#define ASTRIDE      36
#define STAGE_FLOATS (128*ASTRIDE)
#define BUF_FLOATS   (2*STAGE_FLOATS)
#define GEMM_SMEM    (2*BUF_FLOATS*4)

__global__ __launch_bounds__(256) void gemm_tf32_kernel(
    const float* __restrict__ A, const float* __restrict__ BT,
    float* __restrict__ C, float* __restrict__ C2,
    const float* __restrict__ bias, int mode)
{
    extern __shared__ float sm[];
    const int tid  = threadIdx.x;
    const int lane = tid & 31;
    const int wid  = tid >> 5;
    const int wm   = wid & 1;
    const int wn   = wid >> 1;
    const int bx   = blockIdx.x;
    const int by   = blockIdx.y;

    const int lr = tid >> 3;
    const int lq = tid & 7;

    const float* Ag = A  + (size_t)(by * 128 + lr) * DIM + lq * 4;
    const float* Bg = BT + (size_t)(bx * 128 + lr) * DIM + lq * 4;

    float c[4][4][4];
    #pragma unroll
    for (int i = 0; i < 4; i++)
        #pragma unroll
        for (int j = 0; j < 4; j++)
            #pragma unroll
            for (int k = 0; k < 4; k++)
                c[i][j][k] = 0.0f;

    float4 pa[4], pb[4];
    #pragma unroll
    for (int j = 0; j < 4; j++) {
        pa[j] = *reinterpret_cast<const float4*>(Ag + (size_t)j * 32 * DIM);
        pb[j] = *reinterpret_cast<const float4*>(Bg + (size_t)j * 32 * DIM);
    }

    auto store_stage = [&](int b) {
        float* As = sm + b * BUF_FLOATS;
        float* Bs = As + STAGE_FLOATS;
        #pragma unroll
        for (int j = 0; j < 4; j++) {
            uint32_t* uA = reinterpret_cast<uint32_t*>(As + (lr + 32 * j) * ASTRIDE + lq * 4);
            uA[0] = f2tf32(pa[j].x); uA[1] = f2tf32(pa[j].y);
            uA[2] = f2tf32(pa[j].z); uA[3] = f2tf32(pa[j].w);
            *reinterpret_cast<float4*>(Bs + (lr + 32 * j) * ASTRIDE + lq * 4) = pb[j];
        }
    };
    store_stage(0);
    __syncthreads();

    const int NS = DIM / 32;
    for (int s = 0; s < NS; s++) {
        const int cur = s & 1;
        if (s + 1 < NS) {
            const float* Ags = Ag + (s + 1) * 32;
            const float* Bgs = Bg + (s + 1) * 32;
            #pragma unroll
            for (int j = 0; j < 4; j++) {
                pa[j] = *reinterpret_cast<const float4*>(Ags + (size_t)j * 32 * DIM);
                pb[j] = *reinterpret_cast<const float4*>(Bgs + (size_t)j * 32 * DIM);
            }
        }
        const uint32_t* Au = reinterpret_cast<const uint32_t*>(sm + cur * BUF_FLOATS);
        const uint32_t* Bu = Au + STAGE_FLOATS;

        #pragma unroll
        for (int kk = 0; kk < 4; kk++) {
            uint32_t af[4][4], bf[4][2];
            const int col = kk * 8 + (lane & 3);
            const int r0  = wm * 64 + (lane >> 2);
            #pragma unroll
            for (int am = 0; am < 4; am++) {
                const uint32_t* p = Au + (r0 + am * 16) * ASTRIDE + col;
                af[am][0] = p[0];
                af[am][1] = p[8 * ASTRIDE];
                af[am][2] = p[4];
                af[am][3] = p[8 * ASTRIDE + 4];
            }
            #pragma unroll
            for (int bn = 0; bn < 4; bn++) {
                const uint32_t* p = Bu + (wn * 32 + bn * 8 + (lane >> 2)) * ASTRIDE + col;
                bf[bn][0] = p[0];
                bf[bn][1] = p[4];
            }
            #pragma unroll
            for (int am = 0; am < 4; am++)
                #pragma unroll
                for (int bn = 0; bn < 4; bn++)
                    MMA_TF32(c[am][bn], af[am], bf[bn]);
        }

        if (s + 1 < NS) {
            store_stage(1 - cur);
            __syncthreads();
        }
    }

    const int rbase = by * 128 + wm * 64 + (lane >> 2);
    const int cbase = bx * 128 + wn * 32 + (lane & 3) * 2;
    #pragma unroll
    for (int am = 0; am < 4; am++) {
        #pragma unroll
        for (int bn = 0; bn < 4; bn++) {
            const int col = cbase + bn * 8;
            const int r0  = rbase + am * 16;
            float v[4] = {c[am][bn][0], c[am][bn][1], c[am][bn][2], c[am][bn][3]};
            if (mode == 0) {
                float b0 = bias[col], b1 = bias[col + 1];
                *reinterpret_cast<float2*>(C + (size_t)r0 * DIM + col) =
                    make_float2(v[0] + b0, v[1] + b1);
                *reinterpret_cast<float2*>(C + (size_t)(r0 + 8) * DIM + col) =
                    make_float2(v[2] + b0, v[3] + b1);
            } else if (mode == 1) {
                *reinterpret_cast<float2*>(C + (size_t)r0 * DIM + col) =
                    make_float2(v[0] * 0.125f, v[1] * 0.125f);
                *reinterpret_cast<float2*>(C + (size_t)(r0 + 8) * DIM + col) =
                    make_float2(v[2] * 0.125f, v[3] * 0.125f);
            } else if (mode == 2) {
                uint32_t hi[4], lo[4];
                #pragma unroll
                for (int e = 0; e < 4; e++) {
                    hi[e] = f2tf32(v[e]);
                    lo[e] = f2tf32(v[e] - __uint_as_float(hi[e]));
                }
                *reinterpret_cast<uint2*>(C  + (size_t)r0 * DIM + col) = make_uint2(hi[0], hi[1]);
                *reinterpret_cast<uint2*>(C  + (size_t)(r0 + 8) * DIM + col) = make_uint2(hi[2], hi[3]);
                *reinterpret_cast<uint2*>(C2 + (size_t)r0 * DIM + col) = make_uint2(lo[0], lo[1]);
                *reinterpret_cast<uint2*>(C2 + (size_t)(r0 + 8) * DIM + col) = make_uint2(lo[2], lo[3]);
            } else {
                *reinterpret_cast<uint2*>(C + (size_t)r0 * DIM + col) =
                    make_uint2(f2tf32(v[0]), f2tf32(v[1]));
                *reinterpret_cast<uint2*>(C + (size_t)(r0 + 8) * DIM + col) =
                    make_uint2(f2tf32(v[2]), f2tf32(v[3]));
            }
        }
    }
}

// ---------------------------------------------------------------------------
// Tensor-core flash attention v3 (tf32 mma.sync, causal).
// 256 threads = 8 warps, 128 q rows/CTA (16 per warp). kv tiles of 64,
// cp.async double-buffered (pure copies: K pre-split hi/lo, V pre-tf32,
// Q pre-scaled — all conversions done in GEMM epilogues).
// ---------------------------------------------------------------------------
#define AST 68
#define TILE_FLOATS (3*64*AST)                 // Khi+Klo+Vs per buffer
#define ATTN_SMEM ((128*AST + 2*TILE_FLOATS)*4)  // 139264 B

__global__ __launch_bounds__(256, 1) void attn_tc_kernel(
    const float* __restrict__ Q, const float* __restrict__ KhiG,
    const float* __restrict__ KloG, const float* __restrict__ VG,
    float* __restrict__ Oout)
{
    extern __shared__ float smem[];
    float* Ps   = smem;                        // [128][AST]: Q then P tiles
    float* Tile = smem + 128 * AST;            // 2 x (Khi|Klo|Vs)[64][AST]

    const int b    = blockIdx.z;
    const int h    = blockIdx.y;
    const int q0   = (gridDim.x - 1 - blockIdx.x) * 128;  // heavy blocks first
    const int tid  = threadIdx.x;
    const int wq   = tid >> 5;       // 0..7
    const int lane = tid & 31;
    const int gid  = lane >> 2;
    const int tig  = lane & 3;

    const size_t hoff = (size_t)b * SEQ * DIM + h * HD;
    const float* Qg  = Q    + hoff;
    const float* Khg = KhiG + hoff;
    const float* Klg = KloG + hoff;
    const float* Vg  = VG   + hoff;

    const uint32_t tile_u32 = smem_u32(Tile);

    // ---- Prologue: Q tile (pre-scaled) -> smem
    #pragma unroll
    for (int i = 0; i < 8; i++) {
        int idx = tid + i * 256;              // 0..2047 float4 slots
        int r = idx >> 4, c = (idx & 15) * 4;
        *reinterpret_cast<float4*>(&Ps[r * AST + c]) =
            *reinterpret_cast<const float4*>(Qg + (size_t)(q0 + r) * DIM + c);
    }
    __syncthreads();

    uint32_t qhi[8][4], qlo[8][4];
    {
        const int rr = wq * 16 + gid;
        #pragma unroll
        for (int kt = 0; kt < 8; kt++) {
            const int cc = kt * 8 + tig;
            float f[4];
            f[0] = Ps[rr * AST + cc];
            f[1] = Ps[(rr + 8) * AST + cc];
            f[2] = Ps[rr * AST + cc + 4];
            f[3] = Ps[(rr + 8) * AST + cc + 4];
            #pragma unroll
            for (int e = 0; e < 4; e++) {
                qhi[kt][e] = f2tf32(f[e]);
                qlo[kt][e] = f2tf32(f[e] - __uint_as_float(qhi[kt][e]));
            }
        }
    }

    float m0 = -1e30f, m1 = -1e30f, l0 = 0.0f, l1 = 0.0f;
    float o[8][4];
    #pragma unroll
    for (int nt = 0; nt < 8; nt++)
        #pragma unroll
        for (int e = 0; e < 4; e++) o[nt][e] = 0.0f;

    const int ntiles = (q0 >> 6) + 2;

    auto prefetch = [&](int t, int buf) {
        const size_t grow = (size_t)(t * 64) * DIM;
        const uint32_t base = tile_u32 + (uint32_t)buf * TILE_FLOATS * 4;
        #pragma unroll
        for (int i = 0; i < 4; i++) {
            int idx = tid + i * 256;          // 0..1023
            int r = idx >> 4, c = (idx & 15) * 4;
            const uint32_t doff = (uint32_t)((r * AST + c) * 4);
            const size_t goff = grow + (size_t)r * DIM + c;
            CP_ASYNC16(base + doff,                    Khg + goff);
            CP_ASYNC16(base + 64*AST*4 + doff,         Klg + goff);
            CP_ASYNC16(base + 2*64*AST*4 + doff,       Vg  + goff);
        }
        CP_COMMIT();
    };

    prefetch(0, 0);

    for (int t = 0; t < ntiles; t++) {
        const int kv0 = t * 64;
        CP_WAIT0();
        __syncthreads();
        if (t + 1 < ntiles) prefetch(t + 1, (t + 1) & 1);

        // Fully-masked warp? (all rows < kv0) -> skip compute
        if (kv0 > q0 + wq * 16 + 15) continue;

        const float* Khi = Tile + (t & 1) * TILE_FLOATS;
        const float* Klo = Khi + 64 * AST;
        const float* Vs  = Klo + 64 * AST;

        // ---- S = Q @ K^T  (3xTF32)
        float s[8][4];
        #pragma unroll
        for (int nt = 0; nt < 8; nt++)
            #pragma unroll
            for (int e = 0; e < 4; e++) s[nt][e] = 0.0f;

        #pragma unroll
        for (int kt = 0; kt < 8; kt++) {
            #pragma unroll
            for (int nt = 0; nt < 8; nt++) {
                const int boff = (nt * 8 + gid) * AST + kt * 8 + tig;
                uint32_t bh[2], bl[2];
                bh[0] = __float_as_uint(Khi[boff]);
                bh[1] = __float_as_uint(Khi[boff + 4]);
                bl[0] = __float_as_uint(Klo[boff]);
                bl[1] = __float_as_uint(Klo[boff + 4]);
                MMA_TF32(s[nt], qhi[kt], bh);
                MMA_TF32(s[nt], qlo[kt], bh);
                MMA_TF32(s[nt], qhi[kt], bl);
            }
        }

        const int r0g = q0 + wq * 16 + gid;
        const int r1g = r0g + 8;
        if (kv0 + 63 > q0 + wq * 16) {    // diagonal straddle -> mask
            #pragma unroll
            for (int nt = 0; nt < 8; nt++) {
                const int c0 = kv0 + nt * 8 + 2 * tig;
                if (c0     > r0g) s[nt][0] = -1e30f;
                if (c0 + 1 > r0g) s[nt][1] = -1e30f;
                if (c0     > r1g) s[nt][2] = -1e30f;
                if (c0 + 1 > r1g) s[nt][3] = -1e30f;
            }
        }

        // ---- Online softmax
        float mx0 = -1e30f, mx1 = -1e30f;
        #pragma unroll
        for (int nt = 0; nt < 8; nt++) {
            mx0 = fmaxf(mx0, fmaxf(s[nt][0], s[nt][1]));
            mx1 = fmaxf(mx1, fmaxf(s[nt][2], s[nt][3]));
        }
        mx0 = fmaxf(mx0, __shfl_xor_sync(0xffffffffu, mx0, 1));
        mx0 = fmaxf(mx0, __shfl_xor_sync(0xffffffffu, mx0, 2));
        mx1 = fmaxf(mx1, __shfl_xor_sync(0xffffffffu, mx1, 1));
        mx1 = fmaxf(mx1, __shfl_xor_sync(0xffffffffu, mx1, 2));

        const float nm0 = fmaxf(m0, mx0);
        const float nm1 = fmaxf(m1, mx1);
        const float sc0 = __expf(m0 - nm0);
        const float sc1 = __expf(m1 - nm1);
        m0 = nm0; m1 = nm1;
        l0 *= sc0; l1 *= sc1;

        float sum0 = 0.0f, sum1 = 0.0f;
        float* pp = Ps + (wq * 16 + gid) * AST + 2 * tig;
        #pragma unroll
        for (int nt = 0; nt < 8; nt++) {
            float p00 = __expf(s[nt][0] - m0);
            float p01 = __expf(s[nt][1] - m0);
            float p10 = __expf(s[nt][2] - m1);
            float p11 = __expf(s[nt][3] - m1);
            sum0 += p00 + p01;
            sum1 += p10 + p11;
            pp[nt * 8]               = __uint_as_float(f2tf32(p00));
            pp[nt * 8 + 1]           = __uint_as_float(f2tf32(p01));
            pp[8 * AST + nt * 8]     = __uint_as_float(f2tf32(p10));
            pp[8 * AST + nt * 8 + 1] = __uint_as_float(f2tf32(p11));
            o[nt][0] *= sc0; o[nt][1] *= sc0;
            o[nt][2] *= sc1; o[nt][3] *= sc1;
        }
        sum0 += __shfl_xor_sync(0xffffffffu, sum0, 1);
        sum0 += __shfl_xor_sync(0xffffffffu, sum0, 2);
        sum1 += __shfl_xor_sync(0xffffffffu, sum1, 1);
        sum1 += __shfl_xor_sync(0xffffffffu, sum1, 2);
        l0 += sum0; l1 += sum1;

        __syncwarp();

        // ---- O += P @ V
        #pragma unroll
        for (int kt = 0; kt < 8; kt++) {
            uint32_t a[4];
            const float* ap = Ps + (wq * 16 + gid) * AST + kt * 8 + tig;
            a[0] = __float_as_uint(ap[0]);
            a[1] = __float_as_uint(ap[8 * AST]);
            a[2] = __float_as_uint(ap[4]);
            a[3] = __float_as_uint(ap[8 * AST + 4]);
            #pragma unroll
            for (int nt = 0; nt < 8; nt++) {
                const float* bp = Vs + (kt * 8 + tig) * AST + nt * 8 + gid;
                uint32_t bb[2];
                bb[0] = __float_as_uint(bp[0]);
                bb[1] = __float_as_uint(bp[4 * AST]);
                MMA_TF32(o[nt], a, bb);
            }
        }
        __syncwarp();
    }

    // ---- Epilogue
    const float inv0 = 1.0f / l0;
    const float inv1 = 1.0f / l1;
    const int r0g = q0 + wq * 16 + gid;
    float* Og = Oout + hoff;
    #pragma unroll
    for (int nt = 0; nt < 8; nt++) {
        const int col = nt * 8 + 2 * tig;
        float2 v0 = make_float2(o[nt][0] * inv0, o[nt][1] * inv0);
        float2 v1 = make_float2(o[nt][2] * inv1, o[nt][3] * inv1);
        *reinterpret_cast<float2*>(Og + (size_t)r0g * DIM + col)       = v0;
        *reinterpret_cast<float2*>(Og + (size_t)(r0g + 8) * DIM + col) = v1;
    }
}

// ---------------------------------------------------------------------------
// Launch
// ---------------------------------------------------------------------------
extern "C" void kernel_launch(void* const* d_in, const int* in_sizes, int n_in,
                              void* d_out, int out_size)
{
    const float* x  = (const float*)d_in[0];
    const float* Wq = (const float*)d_in[1];
    const float* Wk = (const float*)d_in[2];
    const float* Wv = (const float*)d_in[3];
    const float* Wo = (const float*)d_in[4];
    const float* bo = (const float*)d_in[5];
    float* out = (float*)d_out;

    float *qp, *khp, *klp, *vp, *ap, *wqt, *wkt, *wvt, *wot;
    cudaGetSymbolAddress((void**)&qp,  g_q);
    cudaGetSymbolAddress((void**)&khp, g_khi);
    cudaGetSymbolAddress((void**)&klp, g_klo);
    cudaGetSymbolAddress((void**)&vp,  g_v);
    cudaGetSymbolAddress((void**)&ap,  g_a);
    cudaGetSymbolAddress((void**)&wqt, g_wqt);
    cudaGetSymbolAddress((void**)&wkt, g_wkt);
    cudaGetSymbolAddress((void**)&wvt, g_wvt);
    cudaGetSymbolAddress((void**)&wot, g_wot);

    cudaFuncSetAttribute(gemm_tf32_kernel,
                         cudaFuncAttributeMaxDynamicSharedMemorySize, GEMM_SMEM);
    cudaFuncSetAttribute(attn_tc_kernel,
                         cudaFuncAttributeMaxDynamicSharedMemorySize, ATTN_SMEM);

    dim3 wt_grid(DIM / 32, DIM / 32);
    dim3 wt_block(32, 8);
    transpose_tf32_kernel<<<wt_grid, wt_block>>>(Wq, wqt);
    transpose_tf32_kernel<<<wt_grid, wt_block>>>(Wk, wkt);
    transpose_tf32_kernel<<<wt_grid, wt_block>>>(Wv, wvt);
    transpose_tf32_kernel<<<wt_grid, wt_block>>>(Wo, wot);

    dim3 gemm_grid(DIM / 128, MTOT / 128);   // (8, 32)
    gemm_tf32_kernel<<<gemm_grid, 256, GEMM_SMEM>>>(x, wqt, qp,  nullptr, nullptr, 1);
    gemm_tf32_kernel<<<gemm_grid, 256, GEMM_SMEM>>>(x, wkt, khp, klp,     nullptr, 2);
    gemm_tf32_kernel<<<gemm_grid, 256, GEMM_SMEM>>>(x, wvt, vp,  nullptr, nullptr, 3);

    dim3 attn_grid(SEQ / 128, NH, BATCH);    // (16, 16, 2)
    attn_tc_kernel<<<attn_grid, 256, ATTN_SMEM>>>(qp, khp, klp, vp, ap);

    gemm_tf32_kernel<<<gemm_grid, 256, GEMM_SMEM>>>(ap, wot, out, nullptr, bo, 0);
}

// round 7
// speedup vs baseline: 1.0029x; 1.0029x over previous
#include <cuda_runtime.h>
#include <math.h>
#include <stdint.h>

#define BATCH 2
#define SEQ   2048
#define DIM   1024
#define NH    16
#define HD    64
#define MTOT  (BATCH*SEQ)   // 4096

// ---------------------------------------------------------------------------
// Scratch (allocation-free rule: __device__ globals)
// ---------------------------------------------------------------------------
__device__ float g_q[MTOT*DIM];
__device__ float g_k[MTOT*DIM];
__device__ float g_v[MTOT*DIM];
__device__ float g_a[MTOT*DIM];
// Transposed weights, stored as tf32 bit patterns: WT[n][k] = tf32(W[k][n])
__device__ float g_wqt[DIM*DIM];
__device__ float g_wkt[DIM*DIM];
__device__ float g_wvt[DIM*DIM];
__device__ float g_wot[DIM*DIM];

struct Ptr3 { const float* BT[3]; float* C[3]; };
struct Ptr4 { const float* W[4]; float* WT[4]; };

// ---------------------------------------------------------------------------
// Helpers
// ---------------------------------------------------------------------------
__device__ __forceinline__ uint32_t f2tf32(float f) {
    uint32_t u;
    asm("cvt.rna.tf32.f32 %0, %1;" : "=r"(u) : "f"(f));
    return u;
}

#define MMA_TF32(d, a, b) \
    asm volatile("mma.sync.aligned.m16n8k8.row.col.f32.tf32.tf32.f32 " \
        "{%0,%1,%2,%3}, {%4,%5,%6,%7}, {%8,%9}, {%0,%1,%2,%3};" \
        : "+f"((d)[0]), "+f"((d)[1]), "+f"((d)[2]), "+f"((d)[3]) \
        : "r"((a)[0]), "r"((a)[1]), "r"((a)[2]), "r"((a)[3]), \
          "r"((b)[0]), "r"((b)[1]))

// ---------------------------------------------------------------------------
// Fused transpose + tf32-convert: 4 weights in one launch (z selects)
// ---------------------------------------------------------------------------
__global__ __launch_bounds__(256) void transpose_tf32_kernel(Ptr4 p)
{
    __shared__ float tile[32][33];
    const float* W  = p.W[blockIdx.z];
    float*       WT = p.WT[blockIdx.z];
    const int k0 = blockIdx.y * 32;
    const int n0 = blockIdx.x * 32;
    const int tx = threadIdx.x;
    const int ty = threadIdx.y;
    #pragma unroll
    for (int i = ty; i < 32; i += 8)
        tile[i][tx] = W[(size_t)(k0 + i) * DIM + n0 + tx];
    __syncthreads();
    #pragma unroll
    for (int i = ty; i < 32; i += 8) {
        uint32_t u = f2tf32(tile[tx][i]);
        reinterpret_cast<uint32_t*>(WT)[(size_t)(n0 + i) * DIM + k0 + tx] = u;
    }
}

// ---------------------------------------------------------------------------
// tf32 tensor-core GEMM core (proven R4/R5 config).
// nb==3: fused QKV (blockIdx.z selects BT/C), no bias.
// nb==1: output projection, + bias.
// ---------------------------------------------------------------------------
#define ASTRIDE      36
#define STAGE_FLOATS (128*ASTRIDE)
#define BUF_FLOATS   (2*STAGE_FLOATS)
#define GEMM_SMEM    (2*BUF_FLOATS*4)

__device__ __forceinline__ void gemm_body(
    const float* __restrict__ A, const float* __restrict__ BT,
    float* __restrict__ C, const float* __restrict__ bias)
{
    extern __shared__ float sm[];
    const int tid  = threadIdx.x;
    const int lane = tid & 31;
    const int wid  = tid >> 5;
    const int wm   = wid & 1;
    const int wn   = wid >> 1;
    const int bx   = blockIdx.x;
    const int by   = blockIdx.y;

    const int lr = tid >> 3;
    const int lq = tid & 7;

    const float* Ag = A  + (size_t)(by * 128 + lr) * DIM + lq * 4;
    const float* Bg = BT + (size_t)(bx * 128 + lr) * DIM + lq * 4;

    float c[4][4][4];
    #pragma unroll
    for (int i = 0; i < 4; i++)
        #pragma unroll
        for (int j = 0; j < 4; j++)
            #pragma unroll
            for (int k = 0; k < 4; k++)
                c[i][j][k] = 0.0f;

    float4 pa[4], pb[4];
    #pragma unroll
    for (int j = 0; j < 4; j++) {
        pa[j] = *reinterpret_cast<const float4*>(Ag + (size_t)j * 32 * DIM);
        pb[j] = *reinterpret_cast<const float4*>(Bg + (size_t)j * 32 * DIM);
    }

    auto store_stage = [&](int b) {
        float* As = sm + b * BUF_FLOATS;
        float* Bs = As + STAGE_FLOATS;
        #pragma unroll
        for (int j = 0; j < 4; j++) {
            uint32_t* uA = reinterpret_cast<uint32_t*>(As + (lr + 32 * j) * ASTRIDE + lq * 4);
            uA[0] = f2tf32(pa[j].x); uA[1] = f2tf32(pa[j].y);
            uA[2] = f2tf32(pa[j].z); uA[3] = f2tf32(pa[j].w);
            *reinterpret_cast<float4*>(Bs + (lr + 32 * j) * ASTRIDE + lq * 4) = pb[j];
        }
    };
    store_stage(0);
    __syncthreads();

    const int NS = DIM / 32;
    for (int s = 0; s < NS; s++) {
        const int cur = s & 1;
        if (s + 1 < NS) {
            const float* Ags = Ag + (s + 1) * 32;
            const float* Bgs = Bg + (s + 1) * 32;
            #pragma unroll
            for (int j = 0; j < 4; j++) {
                pa[j] = *reinterpret_cast<const float4*>(Ags + (size_t)j * 32 * DIM);
                pb[j] = *reinterpret_cast<const float4*>(Bgs + (size_t)j * 32 * DIM);
            }
        }
        const uint32_t* Au = reinterpret_cast<const uint32_t*>(sm + cur * BUF_FLOATS);
        const uint32_t* Bu = Au + STAGE_FLOATS;

        #pragma unroll
        for (int kk = 0; kk < 4; kk++) {
            uint32_t af[4][4], bf[4][2];
            const int col = kk * 8 + (lane & 3);
            const int r0  = wm * 64 + (lane >> 2);
            #pragma unroll
            for (int am = 0; am < 4; am++) {
                const uint32_t* p = Au + (r0 + am * 16) * ASTRIDE + col;
                af[am][0] = p[0];
                af[am][1] = p[8 * ASTRIDE];
                af[am][2] = p[4];
                af[am][3] = p[8 * ASTRIDE + 4];
            }
            #pragma unroll
            for (int bn = 0; bn < 4; bn++) {
                const uint32_t* p = Bu + (wn * 32 + bn * 8 + (lane >> 2)) * ASTRIDE + col;
                bf[bn][0] = p[0];
                bf[bn][1] = p[4];
            }
            #pragma unroll
            for (int am = 0; am < 4; am++)
                #pragma unroll
                for (int bn = 0; bn < 4; bn++)
                    MMA_TF32(c[am][bn], af[am], bf[bn]);
        }

        if (s + 1 < NS) {
            store_stage(1 - cur);
            __syncthreads();
        }
    }

    const int rbase = by * 128 + wm * 64 + (lane >> 2);
    const int cbase = bx * 128 + wn * 32 + (lane & 3) * 2;
    #pragma unroll
    for (int am = 0; am < 4; am++) {
        #pragma unroll
        for (int bn = 0; bn < 4; bn++) {
            const int col = cbase + bn * 8;
            const int r0  = rbase + am * 16;
            float b0 = bias ? bias[col]     : 0.0f;
            float b1 = bias ? bias[col + 1] : 0.0f;
            *reinterpret_cast<float2*>(C + (size_t)r0 * DIM + col) =
                make_float2(c[am][bn][0] + b0, c[am][bn][1] + b1);
            *reinterpret_cast<float2*>(C + (size_t)(r0 + 8) * DIM + col) =
                make_float2(c[am][bn][2] + b0, c[am][bn][3] + b1);
        }
    }
}

__global__ __launch_bounds__(256) void gemm_qkv_kernel(const float* __restrict__ A, Ptr3 p)
{
    const int z = blockIdx.z;
    gemm_body(A, p.BT[z], p.C[z], nullptr);
}

__global__ __launch_bounds__(256) void gemm_out_kernel(
    const float* __restrict__ A, const float* __restrict__ BT,
    float* __restrict__ C, const float* __restrict__ bias)
{
    gemm_body(A, BT, C, bias);
}

// ---------------------------------------------------------------------------
// Tensor-core flash attention (tf32 mma.sync, causal) — exact R5 (proven).
// ---------------------------------------------------------------------------
#define AST 68
#define ATTN_SMEM (4*64*AST*4)   // 69632 B

__global__ __launch_bounds__(128, 2) void attn_tc_kernel(
    const float* __restrict__ Q, const float* __restrict__ K,
    const float* __restrict__ V, float* __restrict__ Oout)
{
    extern __shared__ float smem[];
    float* Ps  = smem;
    float* Khi = smem + 64 * AST;
    float* Klo = Khi + 64 * AST;
    float* Vs  = Klo + 64 * AST;

    const int b    = blockIdx.z;
    const int h    = blockIdx.y;
    const int q0   = (gridDim.x - 1 - blockIdx.x) * 64;
    const int tid  = threadIdx.x;
    const int wq   = tid >> 5;
    const int lane = tid & 31;
    const int gid  = lane >> 2;
    const int tig  = lane & 3;

    const float* Qg = Q + (size_t)b * SEQ * DIM + h * HD;
    const float* Kg = K + (size_t)b * SEQ * DIM + h * HD;
    const float* Vg = V + (size_t)b * SEQ * DIM + h * HD;

    #pragma unroll
    for (int i = 0; i < 8; i++) {
        int idx = tid + i * 128;
        int r = idx >> 4, c = (idx & 15) * 4;
        float4 v4 = *reinterpret_cast<const float4*>(Qg + (size_t)(q0 + r) * DIM + c);
        Ps[r * AST + c + 0] = v4.x * 0.125f;
        Ps[r * AST + c + 1] = v4.y * 0.125f;
        Ps[r * AST + c + 2] = v4.z * 0.125f;
        Ps[r * AST + c + 3] = v4.w * 0.125f;
    }
    __syncthreads();

    uint32_t qhi[8][4], qlo[8][4];
    {
        const int rr = wq * 16 + gid;
        #pragma unroll
        for (int kt = 0; kt < 8; kt++) {
            const int cc = kt * 8 + tig;
            float f[4];
            f[0] = Ps[rr * AST + cc];
            f[1] = Ps[(rr + 8) * AST + cc];
            f[2] = Ps[rr * AST + cc + 4];
            f[3] = Ps[(rr + 8) * AST + cc + 4];
            #pragma unroll
            for (int e = 0; e < 4; e++) {
                qhi[kt][e] = f2tf32(f[e]);
                qlo[kt][e] = f2tf32(f[e] - __uint_as_float(qhi[kt][e]));
            }
        }
    }

    float m0 = -1e30f, m1 = -1e30f, l0 = 0.0f, l1 = 0.0f;
    float o[8][4];
    #pragma unroll
    for (int nt = 0; nt < 8; nt++)
        #pragma unroll
        for (int e = 0; e < 4; e++) o[nt][e] = 0.0f;

    const int ntiles = (q0 >> 6) + 1;
    for (int t = 0; t < ntiles; t++) {
        const int kv0 = t * 64;
        __syncthreads();
        #pragma unroll
        for (int i = 0; i < 8; i++) {
            int idx = tid + i * 128;
            int r = idx >> 4, c = (idx & 15) * 4;
            float4 kk = *reinterpret_cast<const float4*>(Kg + (size_t)(kv0 + r) * DIM + c);
            float kv[4] = {kk.x, kk.y, kk.z, kk.w};
            #pragma unroll
            for (int e = 0; e < 4; e++) {
                uint32_t hi = f2tf32(kv[e]);
                Khi[r * AST + c + e] = __uint_as_float(hi);
                Klo[r * AST + c + e] = __uint_as_float(f2tf32(kv[e] - __uint_as_float(hi)));
            }
            float4 vv = *reinterpret_cast<const float4*>(Vg + (size_t)(kv0 + r) * DIM + c);
            Vs[r * AST + c + 0] = __uint_as_float(f2tf32(vv.x));
            Vs[r * AST + c + 1] = __uint_as_float(f2tf32(vv.y));
            Vs[r * AST + c + 2] = __uint_as_float(f2tf32(vv.z));
            Vs[r * AST + c + 3] = __uint_as_float(f2tf32(vv.w));
        }
        __syncthreads();

        float s[8][4];
        #pragma unroll
        for (int nt = 0; nt < 8; nt++)
            #pragma unroll
            for (int e = 0; e < 4; e++) s[nt][e] = 0.0f;

        #pragma unroll
        for (int kt = 0; kt < 8; kt++) {
            #pragma unroll
            for (int nt = 0; nt < 8; nt++) {
                const int boff = (nt * 8 + gid) * AST + kt * 8 + tig;
                uint32_t bh[2], bl[2];
                bh[0] = __float_as_uint(Khi[boff]);
                bh[1] = __float_as_uint(Khi[boff + 4]);
                bl[0] = __float_as_uint(Klo[boff]);
                bl[1] = __float_as_uint(Klo[boff + 4]);
                MMA_TF32(s[nt], qhi[kt], bh);
                MMA_TF32(s[nt], qlo[kt], bh);
                MMA_TF32(s[nt], qhi[kt], bl);
            }
        }

        const int r0g = q0 + wq * 16 + gid;
        const int r1g = r0g + 8;
        if (kv0 == q0) {
            #pragma unroll
            for (int nt = 0; nt < 8; nt++) {
                const int c0 = kv0 + nt * 8 + 2 * tig;
                if (c0     > r0g) s[nt][0] = -1e30f;
                if (c0 + 1 > r0g) s[nt][1] = -1e30f;
                if (c0     > r1g) s[nt][2] = -1e30f;
                if (c0 + 1 > r1g) s[nt][3] = -1e30f;
            }
        }

        float mx0 = -1e30f, mx1 = -1e30f;
        #pragma unroll
        for (int nt = 0; nt < 8; nt++) {
            mx0 = fmaxf(mx0, fmaxf(s[nt][0], s[nt][1]));
            mx1 = fmaxf(mx1, fmaxf(s[nt][2], s[nt][3]));
        }
        mx0 = fmaxf(mx0, __shfl_xor_sync(0xffffffffu, mx0, 1));
        mx0 = fmaxf(mx0, __shfl_xor_sync(0xffffffffu, mx0, 2));
        mx1 = fmaxf(mx1, __shfl_xor_sync(0xffffffffu, mx1, 1));
        mx1 = fmaxf(mx1, __shfl_xor_sync(0xffffffffu, mx1, 2));

        const float nm0 = fmaxf(m0, mx0);
        const float nm1 = fmaxf(m1, mx1);
        const float sc0 = __expf(m0 - nm0);
        const float sc1 = __expf(m1 - nm1);
        m0 = nm0; m1 = nm1;
        l0 *= sc0; l1 *= sc1;

        float sum0 = 0.0f, sum1 = 0.0f;
        float* pp = Ps + (wq * 16 + gid) * AST + 2 * tig;
        #pragma unroll
        for (int nt = 0; nt < 8; nt++) {
            float p00 = __expf(s[nt][0] - m0);
            float p01 = __expf(s[nt][1] - m0);
            float p10 = __expf(s[nt][2] - m1);
            float p11 = __expf(s[nt][3] - m1);
            sum0 += p00 + p01;
            sum1 += p10 + p11;
            pp[nt * 8]               = __uint_as_float(f2tf32(p00));
            pp[nt * 8 + 1]           = __uint_as_float(f2tf32(p01));
            pp[8 * AST + nt * 8]     = __uint_as_float(f2tf32(p10));
            pp[8 * AST + nt * 8 + 1] = __uint_as_float(f2tf32(p11));
            o[nt][0] *= sc0; o[nt][1] *= sc0;
            o[nt][2] *= sc1; o[nt][3] *= sc1;
        }
        sum0 += __shfl_xor_sync(0xffffffffu, sum0, 1);
        sum0 += __shfl_xor_sync(0xffffffffu, sum0, 2);
        sum1 += __shfl_xor_sync(0xffffffffu, sum1, 1);
        sum1 += __shfl_xor_sync(0xffffffffu, sum1, 2);
        l0 += sum0; l1 += sum1;

        __syncwarp();

        #pragma unroll
        for (int kt = 0; kt < 8; kt++) {
            uint32_t a[4];
            const float* ap = Ps + (wq * 16 + gid) * AST + kt * 8 + tig;
            a[0] = __float_as_uint(ap[0]);
            a[1] = __float_as_uint(ap[8 * AST]);
            a[2] = __float_as_uint(ap[4]);
            a[3] = __float_as_uint(ap[8 * AST + 4]);
            #pragma unroll
            for (int nt = 0; nt < 8; nt++) {
                const float* bp = Vs + (kt * 8 + tig) * AST + nt * 8 + gid;
                uint32_t bb[2];
                bb[0] = __float_as_uint(bp[0]);
                bb[1] = __float_as_uint(bp[4 * AST]);
                MMA_TF32(o[nt], a, bb);
            }
        }
        __syncwarp();
    }

    const float inv0 = 1.0f / l0;
    const float inv1 = 1.0f / l1;
    const int r0g = q0 + wq * 16 + gid;
    float* Og = Oout + (size_t)b * SEQ * DIM + h * HD;
    #pragma unroll
    for (int nt = 0; nt < 8; nt++) {
        const int col = nt * 8 + 2 * tig;
        float2 v0 = make_float2(o[nt][0] * inv0, o[nt][1] * inv0);
        float2 v1 = make_float2(o[nt][2] * inv1, o[nt][3] * inv1);
        *reinterpret_cast<float2*>(Og + (size_t)r0g * DIM + col)       = v0;
        *reinterpret_cast<float2*>(Og + (size_t)(r0g + 8) * DIM + col) = v1;
    }
}

// ---------------------------------------------------------------------------
// Launch
// ---------------------------------------------------------------------------
extern "C" void kernel_launch(void* const* d_in, const int* in_sizes, int n_in,
                              void* d_out, int out_size)
{
    const float* x  = (const float*)d_in[0];
    const float* Wq = (const float*)d_in[1];
    const float* Wk = (const float*)d_in[2];
    const float* Wv = (const float*)d_in[3];
    const float* Wo = (const float*)d_in[4];
    const float* bo = (const float*)d_in[5];
    float* out = (float*)d_out;

    float *qp, *kp, *vp, *ap, *wqt, *wkt, *wvt, *wot;
    cudaGetSymbolAddress((void**)&qp,  g_q);
    cudaGetSymbolAddress((void**)&kp,  g_k);
    cudaGetSymbolAddress((void**)&vp,  g_v);
    cudaGetSymbolAddress((void**)&ap,  g_a);
    cudaGetSymbolAddress((void**)&wqt, g_wqt);
    cudaGetSymbolAddress((void**)&wkt, g_wkt);
    cudaGetSymbolAddress((void**)&wvt, g_wvt);
    cudaGetSymbolAddress((void**)&wot, g_wot);

    cudaFuncSetAttribute(gemm_qkv_kernel,
                         cudaFuncAttributeMaxDynamicSharedMemorySize, GEMM_SMEM);
    cudaFuncSetAttribute(gemm_out_kernel,
                         cudaFuncAttributeMaxDynamicSharedMemorySize, GEMM_SMEM);
    cudaFuncSetAttribute(attn_tc_kernel,
                         cudaFuncAttributeMaxDynamicSharedMemorySize, ATTN_SMEM);

    // 1) all 4 weight transposes in one launch
    Ptr4 tp;
    tp.W[0] = Wq;  tp.W[1] = Wk;  tp.W[2] = Wv;  tp.W[3] = Wo;
    tp.WT[0] = wqt; tp.WT[1] = wkt; tp.WT[2] = wvt; tp.WT[3] = wot;
    dim3 wt_grid(DIM / 32, DIM / 32, 4);
    dim3 wt_block(32, 8);
    transpose_tf32_kernel<<<wt_grid, wt_block>>>(tp);

    // 2) fused Q/K/V projections: one launch, 768 CTAs (5.2 waves)
    Ptr3 qkv;
    qkv.BT[0] = wqt; qkv.BT[1] = wkt; qkv.BT[2] = wvt;
    qkv.C[0]  = qp;  qkv.C[1]  = kp;  qkv.C[2]  = vp;
    dim3 gemm_grid(DIM / 128, MTOT / 128, 3);   // (8, 32, 3)
    gemm_qkv_kernel<<<gemm_grid, 256, GEMM_SMEM>>>(x, qkv);

    // 3) attention (R5 proven)
    dim3 attn_grid(SEQ / 64, NH, BATCH);        // (32, 16, 2)
    attn_tc_kernel<<<attn_grid, 128, ATTN_SMEM>>>(qp, kp, vp, ap);

    // 4) output projection (+bias)
    dim3 out_grid(DIM / 128, MTOT / 128);       // (8, 32)
    gemm_out_kernel<<<out_grid, 256, GEMM_SMEM>>>(ap, wot, out, bo);
}